// round 2
// baseline (speedup 1.0000x reference)
#include <cuda_runtime.h>
#include <cuda_bf16.h>

#define BB 4
#define CC 64
#define HH 128
#define WW 128
#define HWW (HH*WW)
#define NPIX (BB*HH*WW)
#define OC 18

#define DCN_PX 64          // pixels per block in k_dcn
#define SPITCH 68          // padded floats per pixel in s-buffer

// Scratch (allocation-free rule: device globals)
__device__ float g_xt[BB*HH*WW*CC];     // NHWC transposed input
__device__ float g_off[NPIX*OC];        // offsets per pixel [18]
__device__ float g_mean[CC];
__device__ float g_istd[CC];
__device__ float2 g_part[512];          // bnstats partials

// ---------------- packed f32x2 helpers ----------------
__device__ __forceinline__ unsigned long long splat2(float x) {
    unsigned long long r;
    asm("mov.b64 %0, {%1, %1};" : "=l"(r) : "f"(x));
    return r;
}
__device__ __forceinline__ unsigned long long fma2(unsigned long long a,
                                                   unsigned long long b,
                                                   unsigned long long c) {
    unsigned long long d;
    asm("fma.rn.f32x2 %0, %1, %2, %3;" : "=l"(d) : "l"(a), "l"(b), "l"(c));
    return d;
}
__device__ __forceinline__ unsigned long long mul2(unsigned long long a,
                                                   unsigned long long b) {
    unsigned long long d;
    asm("mul.rn.f32x2 %0, %1, %2;" : "=l"(d) : "l"(a), "l"(b));
    return d;
}
__device__ __forceinline__ float2 unpk2(unsigned long long v) {
    float2 f;
    asm("mov.b64 {%0, %1}, %2;" : "=f"(f.x), "=f"(f.y) : "l"(v));
    return f;
}

// ---------------------------------------------------------------------------
// Kernel 0: NCHW -> NHWC transpose (tiled via shared, conflict-free)
// ---------------------------------------------------------------------------
__global__ void k_transpose(const float* __restrict__ x) {
    __shared__ float s[64][33];
    int w0 = blockIdx.x * 32;
    int h  = blockIdx.y;
    int b  = blockIdx.z;
    int tx = threadIdx.x, ty = threadIdx.y;
    #pragma unroll
    for (int c = ty; c < 64; c += 8)
        s[c][tx] = x[((b*64 + c)*HH + h)*WW + w0 + tx];
    __syncthreads();
    int pixbase = (b*HH + h)*WW + w0;
    #pragma unroll
    for (int wi = ty; wi < 32; wi += 8) {
        g_xt[(pixbase + wi)*64 + tx]      = s[tx][wi];
        g_xt[(pixbase + wi)*64 + 32 + tx] = s[32 + tx][wi];
    }
}

// ---------------------------------------------------------------------------
// Kernel 1: offset conv 3x3, 64 -> 18 channels, pad 1. (unchanged)
// ---------------------------------------------------------------------------
__global__ __launch_bounds__(256) void k_offconv(const float* __restrict__ ow,
                                                 const float* __restrict__ ob) {
    __shared__ float sW[9 * OC * 64];
    int tid = threadIdx.x;
    for (int i = tid; i < 9 * OC * 64; i += 256) {
        int k = i / (OC * 64);
        int r = i % (OC * 64);
        int och = r / 64;
        int c = r % 64;
        sW[i] = ow[(och * 64 + c) * 9 + k];
    }
    __syncthreads();

    int pid = blockIdx.x * 256 + tid;
    int b = pid / HWW;
    int rem = pid % HWW;
    int h = rem / WW;
    int w = rem % WW;

    float acc[OC];
    #pragma unroll
    for (int o = 0; o < OC; o++) acc[o] = __ldg(ob + o);

    #pragma unroll
    for (int ki = 0; ki < 3; ki++) {
        int y = h - 1 + ki;
        if (y < 0 || y >= HH) continue;
        #pragma unroll
        for (int kj = 0; kj < 3; kj++) {
            int xx = w - 1 + kj;
            if (xx < 0 || xx >= WW) continue;
            const float* px = g_xt + ((b*HH + y)*WW + xx) * 64;
            const float* wk = sW + (ki*3 + kj) * OC * 64;
            #pragma unroll 1
            for (int c0 = 0; c0 < 64; c0 += 4) {
                float4 v = *(const float4*)(px + c0);
                #pragma unroll
                for (int o = 0; o < OC; o++) {
                    float4 wv = *(const float4*)(wk + o*64 + c0);
                    acc[o] += v.x*wv.x + v.y*wv.y + v.z*wv.z + v.w*wv.w;
                }
            }
        }
    }
    float* op = g_off + pid * OC;
    #pragma unroll
    for (int o = 0; o < OC; o++) op[o] = acc[o];
}

// ---------------------------------------------------------------------------
// Kernel 2: deformable sampling + DCN conv, tiled.
// Block = 256 threads, 64 pixels.
//   gather phase : 16 lanes per pixel, coalesced corner loads (2 wf each),
//                  blend with f32x2, stage into padded smem (double buffered)
//   compute phase: thread = (pixel, o-group of 16), weights smem [k][c][o],
//                  packed fma.rn.f32x2 accumulation (8 acc pairs / thread)
// smem: weights 147456 + s-buf 34816 + params 18432 = 200704 B
// ---------------------------------------------------------------------------
__global__ __launch_bounds__(256) void k_dcn(const float* __restrict__ dw,
                                             float* __restrict__ out) {
    extern __shared__ char smem[];
    float*  sW  = (float*)smem;                     // [9][64 c][64 o]
    float*  sS  = (float*)(smem + 147456);          // [2][64 px][68]
    int4*   sPI = (int4*)(smem + 182272);           // [9*64] corner offsets
    float4* sPF = (float4*)(smem + 191488);         // [9*64] corner weights

    const int tid = threadIdx.x;
    const int pixbase = blockIdx.x * DCN_PX;

    // ---- load weights: coalesced LDG.128, scattered STS ----
    // dw layout [o][c][k], smem layout [k][c][o]
    #pragma unroll 4
    for (int it = 0; it < 36; it++) {
        int i4 = tid + it * 256;                    // 9216 float4 total
        float4 v = *(const float4*)(dw + i4 * 4);
        float vv[4] = {v.x, v.y, v.z, v.w};
        #pragma unroll
        for (int e = 0; e < 4; e++) {
            int i = i4 * 4 + e;
            int o = i / 576;
            int r = i % 576;
            int c = r / 9;
            int k = r % 9;
            sW[(k * 64 + c) * 64 + o] = vv[e];
        }
    }

    // ---- precompute sampling params for all (k, px) ----
    for (int t = tid; t < 9 * DCN_PX; t += 256) {
        int k  = t / DCN_PX;
        int px = t % DCN_PX;
        int pid = pixbase + px;
        int b   = pid / HWW;
        int rem = pid % HWW;
        int h   = rem / WW;
        int w   = rem % WW;
        int ki = k / 3, kj = k % 3;
        float dy = g_off[pid * 18 + 2 * k];
        float dx = g_off[pid * 18 + 2 * k + 1];
        float py  = dy + (float)(h - 1 + ki);
        float pxf = dx + (float)(w - 1 + kj);
        float y0f = floorf(py), x0f = floorf(pxf);
        float wy = py - y0f, wx = pxf - x0f;
        int y0 = (int)y0f, x0 = (int)x0f;
        bool vy0 = (y0 >= 0)  && (y0 <= HH - 1);
        bool vy1 = (y0 >= -1) && (y0 <= HH - 2);
        bool vx0 = (x0 >= 0)  && (x0 <= WW - 1);
        bool vx1 = (x0 >= -1) && (x0 <= WW - 2);
        float4 wv;
        wv.x = (1.f - wy) * (1.f - wx) * ((vy0 && vx0) ? 1.f : 0.f);
        wv.y = (1.f - wy) * wx         * ((vy0 && vx1) ? 1.f : 0.f);
        wv.z = wy * (1.f - wx)         * ((vy1 && vx0) ? 1.f : 0.f);
        wv.w = wy * wx                 * ((vy1 && vx1) ? 1.f : 0.f);
        int y0c = min(max(y0, 0), HH - 1), y1c = min(max(y0 + 1, 0), HH - 1);
        int x0c = min(max(x0, 0), WW - 1), x1c = min(max(x0 + 1, 0), WW - 1);
        int rowb = b * HH;
        int4 iv;
        iv.x = ((rowb + y0c) * WW + x0c) * 64;
        iv.y = ((rowb + y0c) * WW + x1c) * 64;
        iv.z = ((rowb + y1c) * WW + x0c) * 64;
        iv.w = ((rowb + y1c) * WW + x1c) * 64;
        sPI[t] = iv;
        sPF[t] = wv;
    }
    __syncthreads();

    const int q   = tid & 15;        // channel chunk within pixel (gather)
    const int sub = tid >> 4;        // 0..15 (gather pixel within pass)
    const int cpx = tid & 63;        // compute pixel
    const int og  = tid >> 6;        // compute o-group (16 o's)

    // gather: stage blended samples for tap k into buf
    auto gather = [&](int k, float* buf) {
        ulonglong2 a[4][4];
        float4 wv4[4];
        #pragma unroll
        for (int p = 0; p < 4; p++) {
            int px = p * 16 + sub;
            int4 iv  = sPI[k * DCN_PX + px];
            wv4[p]   = sPF[k * DCN_PX + px];
            a[p][0] = *(const ulonglong2*)(g_xt + iv.x + q * 4);
            a[p][1] = *(const ulonglong2*)(g_xt + iv.y + q * 4);
            a[p][2] = *(const ulonglong2*)(g_xt + iv.z + q * 4);
            a[p][3] = *(const ulonglong2*)(g_xt + iv.w + q * 4);
        }
        #pragma unroll
        for (int p = 0; p < 4; p++) {
            int px = p * 16 + sub;
            unsigned long long W0 = splat2(wv4[p].x);
            unsigned long long W1 = splat2(wv4[p].y);
            unsigned long long W2 = splat2(wv4[p].z);
            unsigned long long W3 = splat2(wv4[p].w);
            unsigned long long lo = mul2(a[p][0].x, W0);
            lo = fma2(a[p][1].x, W1, lo);
            lo = fma2(a[p][2].x, W2, lo);
            lo = fma2(a[p][3].x, W3, lo);
            unsigned long long hi = mul2(a[p][0].y, W0);
            hi = fma2(a[p][1].y, W1, hi);
            hi = fma2(a[p][2].y, W2, hi);
            hi = fma2(a[p][3].y, W3, hi);
            ulonglong2 s; s.x = lo; s.y = hi;
            *(ulonglong2*)(buf + px * SPITCH + q * 4) = s;
        }
    };

    unsigned long long acc[8];
    #pragma unroll
    for (int j = 0; j < 8; j++) acc[j] = 0ULL;

    // compute: accumulate tap k from buf into acc (16 o's per thread)
    auto compute = [&](int k, const float* buf) {
        const float* sb = buf + cpx * SPITCH;
        const float* wk = sW + k * 4096 + og * 16;
        #pragma unroll 2
        for (int c4 = 0; c4 < 16; c4++) {
            float4 s4 = *(const float4*)(sb + c4 * 4);
            float sv[4] = {s4.x, s4.y, s4.z, s4.w};
            #pragma unroll
            for (int e = 0; e < 4; e++) {
                unsigned long long s2 = splat2(sv[e]);
                const ulonglong2* wr =
                    (const ulonglong2*)(wk + (c4 * 4 + e) * 64);
                #pragma unroll
                for (int jj = 0; jj < 4; jj++) {
                    ulonglong2 wv = wr[jj];
                    acc[jj * 2]     = fma2(s2, wv.x, acc[jj * 2]);
                    acc[jj * 2 + 1] = fma2(s2, wv.y, acc[jj * 2 + 1]);
                }
            }
        }
    };

    gather(0, sS);
    __syncthreads();
    #pragma unroll 1
    for (int k = 0; k < 9; k++) {
        if (k < 8) gather(k + 1, sS + ((k + 1) & 1) * (DCN_PX * SPITCH));
        compute(k, sS + (k & 1) * (DCN_PX * SPITCH));
        __syncthreads();
    }

    // write NCHW output, coalesced across lanes (consecutive rem)
    int pid = pixbase + cpx;
    int b = pid / HWW, rem = pid % HWW;
    #pragma unroll
    for (int j = 0; j < 8; j++) {
        float2 f = unpk2(acc[j]);
        int o = og * 16 + 2 * j;
        out[(b * 64 + o) * HWW + rem]       = f.x;
        out[(b * 64 + o + 1) * HWW + rem]   = f.y;
    }
}

// ---------------------------------------------------------------------------
// Kernel 3a: per-channel partial sums (512 blocks: 64 ch x 8 slices)
// ---------------------------------------------------------------------------
__global__ __launch_bounds__(256) void k_bnstats1(const float* __restrict__ out) {
    int o = blockIdx.x & 63;
    int s = blockIdx.x >> 6;
    float sum = 0.f, sq = 0.f;
    for (int i = threadIdx.x; i < 8192; i += 256) {
        int idx = s * 8192 + i;            // flat index within channel
        int b = idx >> 14;                 // / HWW
        int r = idx & (HWW - 1);
        float v = out[(b * 64 + o) * HWW + r];
        sum += v;
        sq  += v * v;
    }
    #pragma unroll
    for (int off = 16; off; off >>= 1) {
        sum += __shfl_xor_sync(0xffffffffu, sum, off);
        sq  += __shfl_xor_sync(0xffffffffu, sq,  off);
    }
    __shared__ float2 red[8];
    if ((threadIdx.x & 31) == 0) red[threadIdx.x >> 5] = make_float2(sum, sq);
    __syncthreads();
    if (threadIdx.x == 0) {
        float ts = 0.f, tq = 0.f;
        #pragma unroll
        for (int i = 0; i < 8; i++) { ts += red[i].x; tq += red[i].y; }
        g_part[blockIdx.x] = make_float2(ts, tq);
    }
}

// ---------------------------------------------------------------------------
// Kernel 3b: finalize mean / istd
// ---------------------------------------------------------------------------
__global__ void k_bnfin() {
    int o = threadIdx.x;                   // 64 threads
    float s = 0.f, q = 0.f;
    #pragma unroll
    for (int j = 0; j < 8; j++) {
        float2 p = g_part[j * 64 + o];
        s += p.x; q += p.y;
    }
    float inv_n = 1.f / (float)(BB * HWW);
    float mean = s * inv_n;
    float var  = q * inv_n - mean * mean;
    g_mean[o] = mean;
    g_istd[o] = rsqrtf(var + 1e-5f);
}

// ---------------------------------------------------------------------------
// Kernel 4: normalize + affine + ReLU, in place on d_out. float4 vectorized.
// ---------------------------------------------------------------------------
__global__ __launch_bounds__(256) void k_bnapply(float* __restrict__ out,
                                                 const float* __restrict__ gamma,
                                                 const float* __restrict__ beta) {
    int i4 = blockIdx.x * 256 + threadIdx.x;
    int i = i4 * 4;
    int o = (i / HWW) % 64;
    float scale = g_istd[o] * __ldg(gamma + o);
    float shift = __ldg(beta + o) - g_mean[o] * scale;
    float4 v = *((float4*)out + i4);
    v.x = fmaxf(v.x * scale + shift, 0.f);
    v.y = fmaxf(v.y * scale + shift, 0.f);
    v.z = fmaxf(v.z * scale + shift, 0.f);
    v.w = fmaxf(v.w * scale + shift, 0.f);
    *((float4*)out + i4) = v;
}

// ---------------------------------------------------------------------------
extern "C" void kernel_launch(void* const* d_in, const int* in_sizes, int n_in,
                              void* d_out, int out_size) {
    const float* x     = (const float*)d_in[0];
    const float* ow    = (const float*)d_in[1];
    const float* ob    = (const float*)d_in[2];
    const float* dw    = (const float*)d_in[3];
    const float* gamma = (const float*)d_in[4];
    const float* beta  = (const float*)d_in[5];
    float* out = (float*)d_out;

    dim3 tb(32, 8);
    k_transpose<<<dim3(WW / 32, HH, BB), tb>>>(x);

    k_offconv<<<NPIX / 256, 256>>>(ow, ob);

    const int dcn_smem = 200704;
    cudaFuncSetAttribute(k_dcn, cudaFuncAttributeMaxDynamicSharedMemorySize, dcn_smem);
    k_dcn<<<NPIX / DCN_PX, 256, dcn_smem>>>(dw, out);

    k_bnstats1<<<512, 256>>>(out);
    k_bnfin<<<1, 64>>>();

    k_bnapply<<<(BB * 64 * HWW / 4) / 256, 256>>>(out, gamma, beta);
}

// round 3
// speedup vs baseline: 1.4697x; 1.4697x over previous
#include <cuda_runtime.h>
#include <cuda_bf16.h>

#define BB 4
#define CC 64
#define HH 128
#define WW 128
#define HWW (HH*WW)
#define NPIX (BB*HH*WW)
#define OC 18

#define DCN_PX 64          // pixels per tile in k_dcn
#define SPITCH 68          // padded floats per pixel in s-buffer
#define NTILES (NPIX/DCN_PX)
#define DCN_GRID 148

// Scratch (allocation-free rule: device globals)
__device__ float g_xt[BB*HH*WW*CC];       // NHWC transposed input
__device__ float g_off[NPIX*20];          // offsets per pixel, pitch 20
__device__ float g_wt[9*64*64];           // dcn weights [k][c][o]
__device__ float g_owt[9*64*20];          // offset-conv weights [k][c][20]
__device__ float g_mean[CC];
__device__ float g_istd[CC];
__device__ float2 g_part[512];            // bnstats partials

// ---------------- packed f32x2 helpers ----------------
__device__ __forceinline__ unsigned long long splat2(float x) {
    unsigned long long r;
    asm("mov.b64 %0, {%1, %1};" : "=l"(r) : "f"(x));
    return r;
}
__device__ __forceinline__ unsigned long long pack2(float x, float y) {
    unsigned long long r;
    asm("mov.b64 %0, {%1, %2};" : "=l"(r) : "f"(x), "f"(y));
    return r;
}
__device__ __forceinline__ unsigned long long fma2(unsigned long long a,
                                                   unsigned long long b,
                                                   unsigned long long c) {
    unsigned long long d;
    asm("fma.rn.f32x2 %0, %1, %2, %3;" : "=l"(d) : "l"(a), "l"(b), "l"(c));
    return d;
}
__device__ __forceinline__ unsigned long long mul2(unsigned long long a,
                                                   unsigned long long b) {
    unsigned long long d;
    asm("mul.rn.f32x2 %0, %1, %2;" : "=l"(d) : "l"(a), "l"(b));
    return d;
}
__device__ __forceinline__ float2 unpk2(unsigned long long v) {
    float2 f;
    asm("mov.b64 {%0, %1}, %2;" : "=f"(f.x), "=f"(f.y) : "l"(v));
    return f;
}

// ---------------------------------------------------------------------------
// Kernel P: one-time weight transposes.
// g_wt[(k*64+c)*64+o]  = dw[(o*64+c)*9+k]
// g_owt[(k*64+c)*20+o] = ow[(o*64+c)*9+k]  (o<18, pad 0)
// ---------------------------------------------------------------------------
__global__ void k_prep(const float* __restrict__ dw, const float* __restrict__ ow) {
    int idx = blockIdx.x * 256 + threadIdx.x;
    if (idx < 9*64*64) {
        int k = idx / 4096;
        int r = idx % 4096;
        int c = r / 64;
        int o = r % 64;
        g_wt[idx] = dw[(o*64 + c)*9 + k];
    } else {
        int j = idx - 9*64*64;
        if (j < 9*64*20) {
            int k = j / 1280;
            int r = j % 1280;
            int c = r / 20;
            int o = r % 20;
            g_owt[j] = (o < 18) ? ow[(o*64 + c)*9 + k] : 0.f;
        }
    }
}

// ---------------------------------------------------------------------------
// Kernel 0: NCHW -> NHWC transpose (tiled via shared, conflict-free)
// ---------------------------------------------------------------------------
__global__ void k_transpose(const float* __restrict__ x) {
    __shared__ float s[64][33];
    int w0 = blockIdx.x * 32;
    int h  = blockIdx.y;
    int b  = blockIdx.z;
    int tx = threadIdx.x, ty = threadIdx.y;
    #pragma unroll
    for (int c = ty; c < 64; c += 8)
        s[c][tx] = x[((b*64 + c)*HH + h)*WW + w0 + tx];
    __syncthreads();
    int pixbase = (b*HH + h)*WW + w0;
    #pragma unroll
    for (int wi = ty; wi < 32; wi += 8) {
        g_xt[(pixbase + wi)*64 + tx]      = s[tx][wi];
        g_xt[(pixbase + wi)*64 + 32 + tx] = s[32 + tx][wi];
    }
}

// ---------------------------------------------------------------------------
// Kernel 1: offset conv 3x3, 64 -> 18 channels, pad 1.
// f32x2 accumulation; weights pre-transposed [k][c][20]; linear smem staging.
// ---------------------------------------------------------------------------
__global__ __launch_bounds__(256) void k_offconv(const float* __restrict__ ob) {
    __shared__ float sOW[9 * 64 * 20];          // 46080 B
    int tid = threadIdx.x;
    #pragma unroll
    for (int it = 0; it < 12; it++) {
        int i4 = tid + it * 256;
        if (i4 < 2880)
            ((float4*)sOW)[i4] = ((const float4*)g_owt)[i4];
    }
    __syncthreads();

    int pid = blockIdx.x * 256 + tid;
    int b = pid / HWW;
    int rem = pid % HWW;
    int h = rem / WW;
    int w = rem % WW;

    unsigned long long acc[9];
    #pragma unroll
    for (int j = 0; j < 9; j++) acc[j] = pack2(__ldg(ob + 2*j), __ldg(ob + 2*j + 1));

    #pragma unroll
    for (int ki = 0; ki < 3; ki++) {
        int y = h - 1 + ki;
        if (y < 0 || y >= HH) continue;
        #pragma unroll
        for (int kj = 0; kj < 3; kj++) {
            int xx = w - 1 + kj;
            if (xx < 0 || xx >= WW) continue;
            const float* px = g_xt + ((b*HH + y)*WW + xx) * 64;
            const float* wk = sOW + (ki*3 + kj) * 1280;
            #pragma unroll 2
            for (int c0 = 0; c0 < 16; c0++) {
                float4 v = *(const float4*)(px + c0*4);
                float vv[4] = {v.x, v.y, v.z, v.w};
                #pragma unroll
                for (int e = 0; e < 4; e++) {
                    unsigned long long s2 = splat2(vv[e]);
                    const float* wr = wk + (c0*4 + e) * 20;
                    const ulonglong2* w2 = (const ulonglong2*)wr;
                    ulonglong2 wa = w2[0];
                    ulonglong2 wb = w2[1];
                    unsigned long long wc = *(const unsigned long long*)(wr + 16);
                    acc[0] = fma2(s2, wa.x, acc[0]);
                    acc[1] = fma2(s2, wa.y, acc[1]);
                    acc[2] = fma2(s2, wb.x, acc[2]);
                    acc[3] = fma2(s2, wb.y, acc[3]);
                    acc[8] = fma2(s2, wc,   acc[8]);
                    const ulonglong2* w3 = (const ulonglong2*)(wr + 8);
                    ulonglong2 wd = w3[0];
                    ulonglong2 we = w3[1];
                    acc[4] = fma2(s2, wd.x, acc[4]);
                    acc[5] = fma2(s2, wd.y, acc[5]);
                    acc[6] = fma2(s2, we.x, acc[6]);
                    acc[7] = fma2(s2, we.y, acc[7]);
                }
            }
        }
    }
    float2* op = (float2*)(g_off + pid * 20);
    #pragma unroll
    for (int j = 0; j < 9; j++) op[j] = unpk2(acc[j]);
}

// ---------------------------------------------------------------------------
// Kernel 2: deformable sampling + DCN conv. Persistent blocks, 64-px tiles.
//   gather : 16 lanes/px, coalesced 256B corner loads, f32x2 blend -> smem
//   compute: thread = (px, o-group of 16), weights smem [k][c][o], f32x2 acc
// smem: weights 147456 + s-buf 34816 + params 18432 = 200704 B
// ---------------------------------------------------------------------------
__global__ __launch_bounds__(256) void k_dcn(float* __restrict__ out) {
    extern __shared__ char smem[];
    float*  sW  = (float*)smem;                     // [9][64 c][64 o]
    float*  sS  = (float*)(smem + 147456);          // [2][64 px][68]
    int4*   sPI = (int4*)(smem + 182272);           // [9*64] corner offsets
    float4* sPF = (float4*)(smem + 191488);         // [9*64] corner weights

    const int tid = threadIdx.x;

    // ---- stage weights once: linear coalesced copy ----
    #pragma unroll 4
    for (int it = 0; it < 36; it++) {
        int i4 = tid + it * 256;
        ((float4*)sW)[i4] = ((const float4*)g_wt)[i4];
    }

    const int q   = tid & 15;        // channel chunk within pixel (gather)
    const int sub = tid >> 4;        // 0..15 (gather pixel within pass)
    const int cpx = tid & 63;        // compute pixel
    const int og  = tid >> 6;        // compute o-group (16 o's)

    for (int t = blockIdx.x; t < NTILES; t += DCN_GRID) {
        const int pixbase = t * DCN_PX;

        // ---- precompute sampling params for all (k, px) in tile ----
        __syncthreads();    // protect sPI/sPF & sS from previous tile
        for (int tt = tid; tt < 9 * DCN_PX; tt += 256) {
            int k  = tt / DCN_PX;
            int px = tt % DCN_PX;
            int pid = pixbase + px;
            int b   = pid / HWW;
            int rem = pid % HWW;
            int h   = rem / WW;
            int w   = rem % WW;
            int ki = k / 3, kj = k % 3;
            float2 d = *(const float2*)(g_off + pid * 20 + 2 * k);
            float py  = d.x + (float)(h - 1 + ki);
            float pxf = d.y + (float)(w - 1 + kj);
            float y0f = floorf(py), x0f = floorf(pxf);
            float wy = py - y0f, wx = pxf - x0f;
            int y0 = (int)y0f, x0 = (int)x0f;
            bool vy0 = (y0 >= 0)  && (y0 <= HH - 1);
            bool vy1 = (y0 >= -1) && (y0 <= HH - 2);
            bool vx0 = (x0 >= 0)  && (x0 <= WW - 1);
            bool vx1 = (x0 >= -1) && (x0 <= WW - 2);
            float4 wv;
            wv.x = (1.f - wy) * (1.f - wx) * ((vy0 && vx0) ? 1.f : 0.f);
            wv.y = (1.f - wy) * wx         * ((vy0 && vx1) ? 1.f : 0.f);
            wv.z = wy * (1.f - wx)         * ((vy1 && vx0) ? 1.f : 0.f);
            wv.w = wy * wx                 * ((vy1 && vx1) ? 1.f : 0.f);
            int y0c = min(max(y0, 0), HH - 1), y1c = min(max(y0 + 1, 0), HH - 1);
            int x0c = min(max(x0, 0), WW - 1), x1c = min(max(x0 + 1, 0), WW - 1);
            int rowb = b * HH;
            int4 iv;
            iv.x = ((rowb + y0c) * WW + x0c) * 64;
            iv.y = ((rowb + y0c) * WW + x1c) * 64;
            iv.z = ((rowb + y1c) * WW + x0c) * 64;
            iv.w = ((rowb + y1c) * WW + x1c) * 64;
            sPI[tt] = iv;
            sPF[tt] = wv;
        }
        __syncthreads();

        // gather tap k into buf
        auto gather = [&](int k, float* buf) {
            ulonglong2 a[4][4];
            float4 wv4[4];
            #pragma unroll
            for (int p = 0; p < 4; p++) {
                int px = p * 16 + sub;
                int4 iv  = sPI[k * DCN_PX + px];
                wv4[p]   = sPF[k * DCN_PX + px];
                a[p][0] = *(const ulonglong2*)(g_xt + iv.x + q * 4);
                a[p][1] = *(const ulonglong2*)(g_xt + iv.y + q * 4);
                a[p][2] = *(const ulonglong2*)(g_xt + iv.z + q * 4);
                a[p][3] = *(const ulonglong2*)(g_xt + iv.w + q * 4);
            }
            #pragma unroll
            for (int p = 0; p < 4; p++) {
                int px = p * 16 + sub;
                unsigned long long W0 = splat2(wv4[p].x);
                unsigned long long W1 = splat2(wv4[p].y);
                unsigned long long W2 = splat2(wv4[p].z);
                unsigned long long W3 = splat2(wv4[p].w);
                unsigned long long lo = mul2(a[p][0].x, W0);
                lo = fma2(a[p][1].x, W1, lo);
                lo = fma2(a[p][2].x, W2, lo);
                lo = fma2(a[p][3].x, W3, lo);
                unsigned long long hi = mul2(a[p][0].y, W0);
                hi = fma2(a[p][1].y, W1, hi);
                hi = fma2(a[p][2].y, W2, hi);
                hi = fma2(a[p][3].y, W3, hi);
                ulonglong2 s; s.x = lo; s.y = hi;
                *(ulonglong2*)(buf + px * SPITCH + q * 4) = s;
            }
        };

        unsigned long long acc[8];
        #pragma unroll
        for (int j = 0; j < 8; j++) acc[j] = 0ULL;

        // compute tap k from buf (16 o's per thread)
        auto compute = [&](int k, const float* buf) {
            const float* sb = buf + cpx * SPITCH;
            const float* wkb = sW + k * 4096 + og * 16;
            #pragma unroll 2
            for (int c4 = 0; c4 < 16; c4++) {
                float4 s4 = *(const float4*)(sb + c4 * 4);
                float sv[4] = {s4.x, s4.y, s4.z, s4.w};
                #pragma unroll
                for (int e = 0; e < 4; e++) {
                    unsigned long long s2 = splat2(sv[e]);
                    const ulonglong2* wr =
                        (const ulonglong2*)(wkb + (c4 * 4 + e) * 64);
                    ulonglong2 w0 = wr[0];
                    ulonglong2 w1 = wr[1];
                    acc[0] = fma2(s2, w0.x, acc[0]);
                    acc[1] = fma2(s2, w0.y, acc[1]);
                    acc[2] = fma2(s2, w1.x, acc[2]);
                    acc[3] = fma2(s2, w1.y, acc[3]);
                    ulonglong2 w2 = wr[2];
                    ulonglong2 w3 = wr[3];
                    acc[4] = fma2(s2, w2.x, acc[4]);
                    acc[5] = fma2(s2, w2.y, acc[5]);
                    acc[6] = fma2(s2, w3.x, acc[6]);
                    acc[7] = fma2(s2, w3.y, acc[7]);
                }
            }
        };

        gather(0, sS);
        __syncthreads();
        #pragma unroll 1
        for (int k = 0; k < 9; k++) {
            if (k < 8) gather(k + 1, sS + ((k + 1) & 1) * (DCN_PX * SPITCH));
            compute(k, sS + (k & 1) * (DCN_PX * SPITCH));
            __syncthreads();
        }

        // NCHW write, coalesced across lanes
        int pid = pixbase + cpx;
        int b = pid / HWW, rem = pid % HWW;
        #pragma unroll
        for (int j = 0; j < 8; j++) {
            float2 f = unpk2(acc[j]);
            int o = og * 16 + 2 * j;
            out[(b * 64 + o) * HWW + rem]     = f.x;
            out[(b * 64 + o + 1) * HWW + rem] = f.y;
        }
    }
}

// ---------------------------------------------------------------------------
// Kernel 3a: per-channel partial sums (512 blocks: 64 ch x 8 slices)
// ---------------------------------------------------------------------------
__global__ __launch_bounds__(256) void k_bnstats1(const float* __restrict__ out) {
    int o = blockIdx.x & 63;
    int s = blockIdx.x >> 6;
    float sum = 0.f, sq = 0.f;
    for (int i = threadIdx.x; i < 8192; i += 256) {
        int idx = s * 8192 + i;
        int b = idx >> 14;
        int r = idx & (HWW - 1);
        float v = out[(b * 64 + o) * HWW + r];
        sum += v;
        sq  += v * v;
    }
    #pragma unroll
    for (int off = 16; off; off >>= 1) {
        sum += __shfl_xor_sync(0xffffffffu, sum, off);
        sq  += __shfl_xor_sync(0xffffffffu, sq,  off);
    }
    __shared__ float2 red[8];
    if ((threadIdx.x & 31) == 0) red[threadIdx.x >> 5] = make_float2(sum, sq);
    __syncthreads();
    if (threadIdx.x == 0) {
        float ts = 0.f, tq = 0.f;
        #pragma unroll
        for (int i = 0; i < 8; i++) { ts += red[i].x; tq += red[i].y; }
        g_part[blockIdx.x] = make_float2(ts, tq);
    }
}

__global__ void k_bnfin() {
    int o = threadIdx.x;
    float s = 0.f, q = 0.f;
    #pragma unroll
    for (int j = 0; j < 8; j++) {
        float2 p = g_part[j * 64 + o];
        s += p.x; q += p.y;
    }
    float inv_n = 1.f / (float)(BB * HWW);
    float mean = s * inv_n;
    float var  = q * inv_n - mean * mean;
    g_mean[o] = mean;
    g_istd[o] = rsqrtf(var + 1e-5f);
}

// ---------------------------------------------------------------------------
// Kernel 4: normalize + affine + ReLU, in place on d_out. float4 vectorized.
// ---------------------------------------------------------------------------
__global__ __launch_bounds__(256) void k_bnapply(float* __restrict__ out,
                                                 const float* __restrict__ gamma,
                                                 const float* __restrict__ beta) {
    int i4 = blockIdx.x * 256 + threadIdx.x;
    int i = i4 * 4;
    int o = (i / HWW) % 64;
    float scale = g_istd[o] * __ldg(gamma + o);
    float shift = __ldg(beta + o) - g_mean[o] * scale;
    float4 v = *((float4*)out + i4);
    v.x = fmaxf(v.x * scale + shift, 0.f);
    v.y = fmaxf(v.y * scale + shift, 0.f);
    v.z = fmaxf(v.z * scale + shift, 0.f);
    v.w = fmaxf(v.w * scale + shift, 0.f);
    *((float4*)out + i4) = v;
}

// ---------------------------------------------------------------------------
extern "C" void kernel_launch(void* const* d_in, const int* in_sizes, int n_in,
                              void* d_out, int out_size) {
    const float* x     = (const float*)d_in[0];
    const float* ow    = (const float*)d_in[1];
    const float* ob    = (const float*)d_in[2];
    const float* dw    = (const float*)d_in[3];
    const float* gamma = (const float*)d_in[4];
    const float* beta  = (const float*)d_in[5];
    float* out = (float*)d_out;

    k_prep<<<(9*64*64 + 9*64*20 + 255) / 256, 256>>>(dw, ow);

    dim3 tb(32, 8);
    k_transpose<<<dim3(WW / 32, HH, BB), tb>>>(x);

    k_offconv<<<NPIX / 256, 256>>>(ob);

    const int dcn_smem = 200704;
    cudaFuncSetAttribute(k_dcn, cudaFuncAttributeMaxDynamicSharedMemorySize, dcn_smem);
    k_dcn<<<DCN_GRID, 256, dcn_smem>>>(out);

    k_bnstats1<<<512, 256>>>(out);
    k_bnfin<<<1, 64>>>();

    k_bnapply<<<(BB * 64 * HWW / 4) / 256, 256>>>(out, gamma, beta);
}

// round 4
// speedup vs baseline: 1.7046x; 1.1598x over previous
#include <cuda_runtime.h>
#include <cuda_bf16.h>

#define BB 4
#define CC 64
#define HH 128
#define WW 128
#define HWW (HH*WW)
#define NPIX (BB*HH*WW)
#define OC 18

#define DCN_PX 64
#define PT 68                      // sample-buffer row pitch (floats)
#define NTILES (NPIX/DCN_PX)       // 1024
#define DCN_GRID 148

// Scratch (allocation-free rule: device globals)
__device__ float g_xt[BB*HH*WW*CC];       // NHWC input
__device__ float g_off[NPIX*20];          // offsets, pitch 20
__device__ float g_wt[9*64*64];           // dcn weights [k][c][o]
__device__ float g_owt[9*64*20];          // offset-conv weights [k][c][20]
__device__ float g_mean[CC];
__device__ float g_istd[CC];
__device__ float2 g_part[DCN_GRID*64];    // fused bnstats partials

// ---------------- packed f32x2 helpers ----------------
__device__ __forceinline__ unsigned long long splat2(float x) {
    unsigned long long r;
    asm("mov.b64 %0, {%1, %1};" : "=l"(r) : "f"(x));
    return r;
}
__device__ __forceinline__ unsigned long long pack2(float x, float y) {
    unsigned long long r;
    asm("mov.b64 %0, {%1, %2};" : "=l"(r) : "f"(x), "f"(y));
    return r;
}
__device__ __forceinline__ unsigned long long fma2(unsigned long long a,
                                                   unsigned long long b,
                                                   unsigned long long c) {
    unsigned long long d;
    asm("fma.rn.f32x2 %0, %1, %2, %3;" : "=l"(d) : "l"(a), "l"(b), "l"(c));
    return d;
}
__device__ __forceinline__ unsigned long long mul2(unsigned long long a,
                                                   unsigned long long b) {
    unsigned long long d;
    asm("mul.rn.f32x2 %0, %1, %2;" : "=l"(d) : "l"(a), "l"(b));
    return d;
}
__device__ __forceinline__ unsigned long long add2(unsigned long long a,
                                                   unsigned long long b) {
    unsigned long long d;
    asm("add.rn.f32x2 %0, %1, %2;" : "=l"(d) : "l"(a), "l"(b));
    return d;
}
__device__ __forceinline__ float2 unpk2(unsigned long long v) {
    float2 f;
    asm("mov.b64 {%0, %1}, %2;" : "=f"(f.x), "=f"(f.y) : "l"(v));
    return f;
}

// ---------------------------------------------------------------------------
// Kernel P: one-time weight transposes.
// ---------------------------------------------------------------------------
__global__ void k_prep(const float* __restrict__ dw, const float* __restrict__ ow) {
    int idx = blockIdx.x * 256 + threadIdx.x;
    if (idx < 9*64*64) {
        int k = idx / 4096;
        int r = idx % 4096;
        int c = r / 64;
        int o = r % 64;
        g_wt[idx] = dw[(o*64 + c)*9 + k];
    } else {
        int j = idx - 9*64*64;
        if (j < 9*64*20) {
            int k = j / 1280;
            int r = j % 1280;
            int c = r / 20;
            int o = r % 20;
            g_owt[j] = (o < 18) ? ow[(o*64 + c)*9 + k] : 0.f;
        }
    }
}

// ---------------------------------------------------------------------------
// Kernel 0: NCHW -> NHWC transpose
// ---------------------------------------------------------------------------
__global__ void k_transpose(const float* __restrict__ x) {
    __shared__ float s[64][33];
    int w0 = blockIdx.x * 32;
    int h  = blockIdx.y;
    int b  = blockIdx.z;
    int tx = threadIdx.x, ty = threadIdx.y;
    #pragma unroll
    for (int c = ty; c < 64; c += 8)
        s[c][tx] = x[((b*64 + c)*HH + h)*WW + w0 + tx];
    __syncthreads();
    int pixbase = (b*HH + h)*WW + w0;
    #pragma unroll
    for (int wi = ty; wi < 32; wi += 8) {
        g_xt[(pixbase + wi)*64 + tx]      = s[tx][wi];
        g_xt[(pixbase + wi)*64 + 32 + tx] = s[32 + tx][wi];
    }
}

// ---------------------------------------------------------------------------
// Kernel 1: offset conv 3x3, 64 -> 18ch (f32x2, pre-transposed weights)
// ---------------------------------------------------------------------------
__global__ __launch_bounds__(256) void k_offconv(const float* __restrict__ ob) {
    __shared__ float sOW[9 * 64 * 20];
    int tid = threadIdx.x;
    #pragma unroll
    for (int it = 0; it < 12; it++) {
        int i4 = tid + it * 256;
        if (i4 < 2880)
            ((float4*)sOW)[i4] = ((const float4*)g_owt)[i4];
    }
    __syncthreads();

    int pid = blockIdx.x * 256 + tid;
    int b = pid / HWW;
    int rem = pid % HWW;
    int h = rem / WW;
    int w = rem % WW;

    unsigned long long acc[9];
    #pragma unroll
    for (int j = 0; j < 9; j++) acc[j] = pack2(__ldg(ob + 2*j), __ldg(ob + 2*j + 1));

    #pragma unroll
    for (int ki = 0; ki < 3; ki++) {
        int y = h - 1 + ki;
        if (y < 0 || y >= HH) continue;
        #pragma unroll
        for (int kj = 0; kj < 3; kj++) {
            int xx = w - 1 + kj;
            if (xx < 0 || xx >= WW) continue;
            const float* px = g_xt + ((b*HH + y)*WW + xx) * 64;
            const float* wk = sOW + (ki*3 + kj) * 1280;
            #pragma unroll 2
            for (int c0 = 0; c0 < 16; c0++) {
                float4 v = *(const float4*)(px + c0*4);
                float vv[4] = {v.x, v.y, v.z, v.w};
                #pragma unroll
                for (int e = 0; e < 4; e++) {
                    unsigned long long s2 = splat2(vv[e]);
                    const float* wr = wk + (c0*4 + e) * 20;
                    const ulonglong2* w2 = (const ulonglong2*)wr;
                    ulonglong2 wa = w2[0];
                    ulonglong2 wb = w2[1];
                    unsigned long long wc = *(const unsigned long long*)(wr + 16);
                    acc[0] = fma2(s2, wa.x, acc[0]);
                    acc[1] = fma2(s2, wa.y, acc[1]);
                    acc[2] = fma2(s2, wb.x, acc[2]);
                    acc[3] = fma2(s2, wb.y, acc[3]);
                    acc[8] = fma2(s2, wc,   acc[8]);
                    const ulonglong2* w3 = (const ulonglong2*)(wr + 8);
                    ulonglong2 wd = w3[0];
                    ulonglong2 we = w3[1];
                    acc[4] = fma2(s2, wd.x, acc[4]);
                    acc[5] = fma2(s2, wd.y, acc[5]);
                    acc[6] = fma2(s2, we.x, acc[6]);
                    acc[7] = fma2(s2, we.y, acc[7]);
                }
            }
        }
    }
    float2* op = (float2*)(g_off + pid * 20);
    #pragma unroll
    for (int j = 0; j < 9; j++) op[j] = unpk2(acc[j]);
}

// ---------------------------------------------------------------------------
// Kernel 2: deformable sampling + DCN conv. Persistent, 64-px tiles.
// Sample buffer TRANSPOSED + XOR-swizzled: element (c, px) at
//   c*PT + 4*((px>>2) ^ ((c>>2)&15)) + (px&3)
// Compute thread = (pg 0..7, cs 0..1, og 0..15): 8 px x 4 o, c-split by 2.
// smem: weights 147456 + samples 2*64*68*4=34816 + params 18432 = 200704
// ---------------------------------------------------------------------------
__global__ __launch_bounds__(256) void k_dcn(float* __restrict__ out) {
    extern __shared__ char smem[];
    float*  sW  = (float*)smem;                     // [9][64 c][64 o]
    float*  sS  = (float*)(smem + 147456);          // [2][64][PT]
    int4*   sPI = (int4*)(smem + 182272);           // [9*64]
    float4* sPF = (float4*)(smem + 191488);         // [9*64]
    float*  sRed = (float*)(smem + 147456);         // reused at epilogue

    const int tid = threadIdx.x;

    // stage weights once (linear, coalesced, conflict-free)
    #pragma unroll 4
    for (int it = 0; it < 36; it++) {
        int i4 = tid + it * 256;
        ((float4*)sW)[i4] = ((const float4*)g_wt)[i4];
    }

    // gather mapping
    const int q   = tid & 15;          // channel chunk (4 c's)
    const int sub = tid >> 4;          // pixel-within-pass
    // compute mapping
    const int pg = tid & 7;            // pixel group (4 px); also pg+8
    const int cs = (tid >> 3) & 1;     // c-half
    const int og = tid >> 4;           // 4 o's

    float bsum[4] = {0.f, 0.f, 0.f, 0.f};
    float bsq[4]  = {0.f, 0.f, 0.f, 0.f};

    for (int t = blockIdx.x; t < NTILES; t += DCN_GRID) {
        const int pixbase = t * DCN_PX;

        // ---- sampling params for all (k, px) ----
        for (int tt = tid; tt < 9 * DCN_PX; tt += 256) {
            int k  = tt / DCN_PX;
            int px = tt % DCN_PX;
            int pid = pixbase + px;
            int b   = pid >> 14;
            int rem = pid & (HWW - 1);
            int h   = rem / WW;
            int w   = rem % WW;
            int ki = k / 3, kj = k % 3;
            float2 d = *(const float2*)(g_off + pid * 20 + 2 * k);
            float py  = d.x + (float)(h - 1 + ki);
            float pxf = d.y + (float)(w - 1 + kj);
            float y0f = floorf(py), x0f = floorf(pxf);
            float wy = py - y0f, wx = pxf - x0f;
            int y0 = (int)y0f, x0 = (int)x0f;
            bool vy0 = (y0 >= 0)  && (y0 <= HH - 1);
            bool vy1 = (y0 >= -1) && (y0 <= HH - 2);
            bool vx0 = (x0 >= 0)  && (x0 <= WW - 1);
            bool vx1 = (x0 >= -1) && (x0 <= WW - 2);
            float4 wv;
            wv.x = (1.f - wy) * (1.f - wx) * ((vy0 && vx0) ? 1.f : 0.f);
            wv.y = (1.f - wy) * wx         * ((vy0 && vx1) ? 1.f : 0.f);
            wv.z = wy * (1.f - wx)         * ((vy1 && vx0) ? 1.f : 0.f);
            wv.w = wy * wx                 * ((vy1 && vx1) ? 1.f : 0.f);
            int y0c = min(max(y0, 0), HH - 1), y1c = min(max(y0 + 1, 0), HH - 1);
            int x0c = min(max(x0, 0), WW - 1), x1c = min(max(x0 + 1, 0), WW - 1);
            int rowb = (pid >> 14) * HH;
            int4 iv;
            iv.x = ((rowb + y0c) * WW + x0c) * 64;
            iv.y = ((rowb + y0c) * WW + x1c) * 64;
            iv.z = ((rowb + y1c) * WW + x0c) * 64;
            iv.w = ((rowb + y1c) * WW + x1c) * 64;
            sPI[tt] = iv;
            sPF[tt] = wv;
        }
        __syncthreads();

        ulonglong2 a[4][4];     // raw corners, held across compute
        float4 wv4[4];

        // issue 16 corner LDGs for tap k (no consumption yet)
        auto load_tap = [&](int k) {
            #pragma unroll
            for (int p = 0; p < 4; p++) {
                int px = p * 16 + sub;
                int4 iv = sPI[k * DCN_PX + px];
                wv4[p]  = sPF[k * DCN_PX + px];
                a[p][0] = *(const ulonglong2*)(g_xt + iv.x + q * 4);
                a[p][1] = *(const ulonglong2*)(g_xt + iv.y + q * 4);
                a[p][2] = *(const ulonglong2*)(g_xt + iv.z + q * 4);
                a[p][3] = *(const ulonglong2*)(g_xt + iv.w + q * 4);
            }
        };

        // blend + transposed/swizzled store for tap k
        auto store_tap = [&](float* buf) {
            #pragma unroll
            for (int p = 0; p < 4; p++) {
                int px = p * 16 + sub;
                unsigned long long W0 = splat2(wv4[p].x);
                unsigned long long W1 = splat2(wv4[p].y);
                unsigned long long W2 = splat2(wv4[p].z);
                unsigned long long W3 = splat2(wv4[p].w);
                unsigned long long lo = mul2(a[p][0].x, W0);
                lo = fma2(a[p][1].x, W1, lo);
                lo = fma2(a[p][2].x, W2, lo);
                lo = fma2(a[p][3].x, W3, lo);
                unsigned long long hi = mul2(a[p][0].y, W0);
                hi = fma2(a[p][1].y, W1, hi);
                hi = fma2(a[p][2].y, W2, hi);
                hi = fma2(a[p][3].y, W3, hi);
                float2 f01 = unpk2(lo);
                float2 f23 = unpk2(hi);
                // c = 4q+e  ->  key = (c>>2)&15 = q (same for e=0..3)
                float* base = buf + 4*((px >> 2) ^ q) + (px & 3) + (4*q)*PT;
                base[0]    = f01.x;
                base[PT]   = f01.y;
                base[2*PT] = f23.x;
                base[3*PT] = f23.y;
            }
        };

        unsigned long long acc[4][4];   // [pxpair: A01,A23,B01,B23][o]
        #pragma unroll
        for (int i = 0; i < 4; i++)
            #pragma unroll
            for (int j = 0; j < 4; j++) acc[i][j] = 0ULL;

        auto compute_tap = [&](int k, const float* buf) {
            const float* wkb = sW + k * 4096 + og * 4;
            #pragma unroll 4
            for (int ci = 0; ci < 32; ci++) {
                int c = cs * 32 + ci;
                int key = (c >> 2) & 15;
                const float* row = buf + c * PT;
                ulonglong2 sA = *(const ulonglong2*)(row + 4*(pg ^ key));
                ulonglong2 sB = *(const ulonglong2*)(row + 4*((pg + 8) ^ key));
                float4 w = *(const float4*)(wkb + c * 64);
                unsigned long long w0 = splat2(w.x);
                unsigned long long w1 = splat2(w.y);
                unsigned long long w2 = splat2(w.z);
                unsigned long long w3 = splat2(w.w);
                acc[0][0] = fma2(sA.x, w0, acc[0][0]);
                acc[0][1] = fma2(sA.x, w1, acc[0][1]);
                acc[0][2] = fma2(sA.x, w2, acc[0][2]);
                acc[0][3] = fma2(sA.x, w3, acc[0][3]);
                acc[1][0] = fma2(sA.y, w0, acc[1][0]);
                acc[1][1] = fma2(sA.y, w1, acc[1][1]);
                acc[1][2] = fma2(sA.y, w2, acc[1][2]);
                acc[1][3] = fma2(sA.y, w3, acc[1][3]);
                acc[2][0] = fma2(sB.x, w0, acc[2][0]);
                acc[2][1] = fma2(sB.x, w1, acc[2][1]);
                acc[2][2] = fma2(sB.x, w2, acc[2][2]);
                acc[2][3] = fma2(sB.x, w3, acc[2][3]);
                acc[3][0] = fma2(sB.y, w0, acc[3][0]);
                acc[3][1] = fma2(sB.y, w1, acc[3][1]);
                acc[3][2] = fma2(sB.y, w2, acc[3][2]);
                acc[3][3] = fma2(sB.y, w3, acc[3][3]);
            }
        };

        load_tap(0);
        store_tap(sS);
        __syncthreads();
        #pragma unroll 1
        for (int k = 0; k < 9; k++) {
            if (k < 8) load_tap(k + 1);                     // LDGs in flight
            compute_tap(k, sS + (k & 1) * (64 * PT));       // hide latency
            if (k < 8) store_tap(sS + ((k + 1) & 1) * (64 * PT));
            __syncthreads();
        }

        // reduce the c-split (partner differs in tid bit3 -> lane xor 8)
        #pragma unroll
        for (int i = 0; i < 4; i++)
            #pragma unroll
            for (int j = 0; j < 4; j++) {
                unsigned long long v = __shfl_xor_sync(0xffffffffu, acc[i][j], 8);
                acc[i][j] = add2(acc[i][j], v);
            }

        // write: cs0 -> pixels 4pg..4pg+3 ; cs1 -> pixels 32+4pg..
        int ppb = cs * 2;
        int px0 = pixbase + cs * 32 + pg * 4;
        int b = px0 >> 14;
        int rem0 = px0 & (HWW - 1);
        #pragma unroll
        for (int j = 0; j < 4; j++) {
            int o = og * 4 + j;
            float2 u = unpk2(acc[ppb][j]);
            float2 v = unpk2(acc[ppb + 1][j]);
            float4 st; st.x = u.x; st.y = u.y; st.z = v.x; st.w = v.y;
            *(float4*)(out + (b * 64 + o) * HWW + rem0) = st;
            bsum[j] += u.x + u.y + v.x + v.y;
            bsq[j]  += u.x*u.x + u.y*u.y + v.x*v.x + v.y*v.y;
        }
    }

    // ---- fused BN partials: block reduction over (pg, cs) per o ----
    __syncthreads();
    int gidx = pg | (cs << 3);                  // 0..15 within o-group
    #pragma unroll
    for (int j = 0; j < 4; j++) {
        int o = og * 4 + j;
        sRed[o * 17 + gidx]            = bsum[j];
        sRed[64 * 17 + o * 17 + gidx]  = bsq[j];
    }
    __syncthreads();
    if (tid < 64) {
        float s = 0.f, qq = 0.f;
        #pragma unroll
        for (int i = 0; i < 16; i++) {
            s  += sRed[tid * 17 + i];
            qq += sRed[64 * 17 + tid * 17 + i];
        }
        g_part[blockIdx.x * 64 + tid] = make_float2(s, qq);
    }
}

// ---------------------------------------------------------------------------
// Kernel 3: finalize mean / istd from 148 block partials
// ---------------------------------------------------------------------------
__global__ void k_bnfin() {
    int o = threadIdx.x;
    float s = 0.f, q = 0.f;
    #pragma unroll 4
    for (int j = 0; j < DCN_GRID; j++) {
        float2 p = g_part[j * 64 + o];
        s += p.x; q += p.y;
    }
    float inv_n = 1.f / (float)(BB * HWW);
    float mean = s * inv_n;
    float var  = q * inv_n - mean * mean;
    g_mean[o] = mean;
    g_istd[o] = rsqrtf(var + 1e-5f);
}

// ---------------------------------------------------------------------------
// Kernel 4: normalize + affine + ReLU
// ---------------------------------------------------------------------------
__global__ __launch_bounds__(256) void k_bnapply(float* __restrict__ out,
                                                 const float* __restrict__ gamma,
                                                 const float* __restrict__ beta) {
    int i4 = blockIdx.x * 256 + threadIdx.x;
    int i = i4 * 4;
    int o = (i / HWW) % 64;
    float scale = g_istd[o] * __ldg(gamma + o);
    float shift = __ldg(beta + o) - g_mean[o] * scale;
    float4 v = *((float4*)out + i4);
    v.x = fmaxf(v.x * scale + shift, 0.f);
    v.y = fmaxf(v.y * scale + shift, 0.f);
    v.z = fmaxf(v.z * scale + shift, 0.f);
    v.w = fmaxf(v.w * scale + shift, 0.f);
    *((float4*)out + i4) = v;
}

// ---------------------------------------------------------------------------
extern "C" void kernel_launch(void* const* d_in, const int* in_sizes, int n_in,
                              void* d_out, int out_size) {
    const float* x     = (const float*)d_in[0];
    const float* ow    = (const float*)d_in[1];
    const float* ob    = (const float*)d_in[2];
    const float* dw    = (const float*)d_in[3];
    const float* gamma = (const float*)d_in[4];
    const float* beta  = (const float*)d_in[5];
    float* out = (float*)d_out;

    k_prep<<<(9*64*64 + 9*64*20 + 255) / 256, 256>>>(dw, ow);

    dim3 tb(32, 8);
    k_transpose<<<dim3(WW / 32, HH, BB), tb>>>(x);

    k_offconv<<<NPIX / 256, 256>>>(ob);

    const int dcn_smem = 200704;
    cudaFuncSetAttribute(k_dcn, cudaFuncAttributeMaxDynamicSharedMemorySize, dcn_smem);
    k_dcn<<<DCN_GRID, 256, dcn_smem>>>(out);

    k_bnfin<<<1, 64>>>();

    k_bnapply<<<(BB * 64 * HWW / 4) / 256, 256>>>(out, gamma, beta);
}

// round 5
// speedup vs baseline: 1.9262x; 1.1300x over previous
#include <cuda_runtime.h>
#include <cuda_bf16.h>

#define BB 4
#define CC 64
#define HH 128
#define WW 128
#define HWW (HH*WW)
#define NPIX (BB*HH*WW)

#define DCN_PX 64
#define PT 68                      // sample-buffer row pitch (floats)
#define NTILES (NPIX/DCN_PX)       // 1024
#define DCN_GRID 296

// Scratch (allocation-free rule: device globals)
__device__ float g_xt[BB*HH*WW*CC];       // NHWC input (for dcn gathers)
__device__ float g_off[NPIX*20];          // offsets, pitch 20
__device__ float g_wt[9*64*64];           // dcn weights [k][c][o]
__device__ float g_owt[9*64*20];          // offset-conv weights [k][c][20]
__device__ float g_mean[CC];
__device__ float g_istd[CC];
__device__ float2 g_part[DCN_GRID*64];    // fused bnstats partials

// ---------------- packed f32x2 helpers ----------------
__device__ __forceinline__ unsigned long long splat2(float x) {
    unsigned long long r;
    asm("mov.b64 %0, {%1, %1};" : "=l"(r) : "f"(x));
    return r;
}
__device__ __forceinline__ unsigned long long pack2(float x, float y) {
    unsigned long long r;
    asm("mov.b64 %0, {%1, %2};" : "=l"(r) : "f"(x), "f"(y));
    return r;
}
__device__ __forceinline__ unsigned long long fma2(unsigned long long a,
                                                   unsigned long long b,
                                                   unsigned long long c) {
    unsigned long long d;
    asm("fma.rn.f32x2 %0, %1, %2, %3;" : "=l"(d) : "l"(a), "l"(b), "l"(c));
    return d;
}
__device__ __forceinline__ unsigned long long mul2(unsigned long long a,
                                                   unsigned long long b) {
    unsigned long long d;
    asm("mul.rn.f32x2 %0, %1, %2;" : "=l"(d) : "l"(a), "l"(b));
    return d;
}
__device__ __forceinline__ unsigned long long add2(unsigned long long a,
                                                   unsigned long long b) {
    unsigned long long d;
    asm("add.rn.f32x2 %0, %1, %2;" : "=l"(d) : "l"(a), "l"(b));
    return d;
}
__device__ __forceinline__ float2 unpk2(unsigned long long v) {
    float2 f;
    asm("mov.b64 {%0, %1}, %2;" : "=f"(f.x), "=f"(f.y) : "l"(v));
    return f;
}

// ---------------------------------------------------------------------------
// Kernel P: one-time weight transposes.
// ---------------------------------------------------------------------------
__global__ void k_prep(const float* __restrict__ dw, const float* __restrict__ ow) {
    int idx = blockIdx.x * 256 + threadIdx.x;
    if (idx < 9*64*64) {
        int k = idx / 4096;
        int r = idx % 4096;
        int c = r / 64;
        int o = r % 64;
        g_wt[idx] = dw[(o*64 + c)*9 + k];
    } else {
        int j = idx - 9*64*64;
        if (j < 9*64*20) {
            int k = j / 1280;
            int r = j % 1280;
            int c = r / 20;
            int o = r % 20;
            g_owt[j] = (o < 18) ? ow[(o*64 + c)*9 + k] : 0.f;
        }
    }
}

// ---------------------------------------------------------------------------
// Kernel 0: NCHW -> NHWC transpose
// ---------------------------------------------------------------------------
__global__ void k_transpose(const float* __restrict__ x) {
    __shared__ float s[64][33];
    int w0 = blockIdx.x * 32;
    int h  = blockIdx.y;
    int b  = blockIdx.z;
    int tx = threadIdx.x, ty = threadIdx.y;
    #pragma unroll
    for (int c = ty; c < 64; c += 8)
        s[c][tx] = x[((b*64 + c)*HH + h)*WW + w0 + tx];
    __syncthreads();
    int pixbase = (b*HH + h)*WW + w0;
    #pragma unroll
    for (int wi = ty; wi < 32; wi += 8) {
        g_xt[(pixbase + wi)*64 + tx]      = s[tx][wi];
        g_xt[(pixbase + wi)*64 + 32 + tx] = s[32 + tx][wi];
    }
}

// ---------------------------------------------------------------------------
// Kernel 1: offset conv 3x3, 64 -> 18ch.  Reads NCHW x directly (coalesced).
// Block = 2 output rows x 128 w. smem: weights 46080B + xtile 32768B = 78848.
// xtile [16c][4rows][128w] per c-chunk; 4 chunks.
// ---------------------------------------------------------------------------
__global__ __launch_bounds__(256) void k_offconv(const float* __restrict__ x,
                                                 const float* __restrict__ ob) {
    extern __shared__ float sm[];
    float* sOW = sm;                 // 11520 floats
    float* xt  = sm + 11520;         // 8192 floats

    int tid = threadIdx.x;
    for (int i4 = tid; i4 < 2880; i4 += 256)
        ((float4*)sOW)[i4] = ((const float4*)g_owt)[i4];

    int b  = blockIdx.x >> 6;
    int y0 = (blockIdx.x & 63) * 2;
    int py = tid >> 7;               // 0..1
    int w  = tid & 127;

    unsigned long long acc[9];
    #pragma unroll
    for (int j = 0; j < 9; j++) acc[j] = pack2(__ldg(ob + 2*j), __ldg(ob + 2*j + 1));

    #pragma unroll 1
    for (int cc = 0; cc < 4; cc++) {
        __syncthreads();
        // stage xtile: rows y0-1..y0+2, channels cc*16..cc*16+15 (coalesced)
        #pragma unroll
        for (int j = 0; j < 8; j++) {
            int i4 = tid + j * 256;                 // 2048 float4 total
            int ci = i4 >> 7;
            int r  = (i4 >> 5) & 3;
            int w4 = i4 & 31;
            int yr = y0 - 1 + r;
            float4 v = make_float4(0.f, 0.f, 0.f, 0.f);
            if (yr >= 0 && yr < HH)
                v = *((const float4*)(x + ((b*64 + cc*16 + ci)*HH + yr)*WW) + w4);
            ((float4*)xt)[i4] = v;
        }
        __syncthreads();

        #pragma unroll
        for (int ki = 0; ki < 3; ki++) {
            int r = py + ki;
            #pragma unroll
            for (int kj = 0; kj < 3; kj++) {
                int xx = w - 1 + kj;
                if (xx < 0 || xx >= WW) continue;
                const float* wk0 = sOW + ((ki*3 + kj)*64 + cc*16) * 20;
                const float* xr = xt + r*128 + xx;
                #pragma unroll 4
                for (int ci = 0; ci < 16; ci++) {
                    unsigned long long s2 = splat2(xr[ci * 512]);
                    const float* wr = wk0 + ci * 20;
                    const ulonglong2* w2 = (const ulonglong2*)wr;
                    ulonglong2 wa = w2[0];
                    ulonglong2 wb = w2[1];
                    unsigned long long wc = *(const unsigned long long*)(wr + 16);
                    acc[0] = fma2(s2, wa.x, acc[0]);
                    acc[1] = fma2(s2, wa.y, acc[1]);
                    acc[2] = fma2(s2, wb.x, acc[2]);
                    acc[3] = fma2(s2, wb.y, acc[3]);
                    acc[8] = fma2(s2, wc,   acc[8]);
                    const ulonglong2* w3 = (const ulonglong2*)(wr + 8);
                    ulonglong2 wd = w3[0];
                    ulonglong2 we = w3[1];
                    acc[4] = fma2(s2, wd.x, acc[4]);
                    acc[5] = fma2(s2, wd.y, acc[5]);
                    acc[6] = fma2(s2, we.x, acc[6]);
                    acc[7] = fma2(s2, we.y, acc[7]);
                }
            }
        }
    }
    int pid = b * HWW + (y0 + py) * WW + w;
    float2* op = (float2*)(g_off + pid * 20);
    #pragma unroll
    for (int j = 0; j < 9; j++) op[j] = unpk2(acc[j]);
}

// ---------------------------------------------------------------------------
// Kernel 2: deformable sampling + DCN conv. Persistent, 64-px tiles.
// Weights staged per-tap via cp.async (16KB, double buffered).
// smem: samples 2x17408 + weights 2x16384 + params 18432 = 86016 B -> 2 blk/SM
// ---------------------------------------------------------------------------
__global__ __launch_bounds__(256, 2) void k_dcn(float* __restrict__ out) {
    extern __shared__ char smem[];
    float*  sS  = (float*)smem;                     // [2][64][PT]
    float*  sWb = (float*)(smem + 34816);           // [2][4096]
    int4*   sPI = (int4*)(smem + 67584);            // [9*64]
    float4* sPF = (float4*)(smem + 76800);          // [9*64]
    float*  sRed = (float*)(smem + 34816);          // epilogue reuse

    const int tid = threadIdx.x;

    // gather mapping
    const int q   = tid & 15;          // channel chunk (4 c's)
    const int sub = tid >> 4;          // pixel-within-pass
    // compute mapping
    const int pg = tid & 7;            // pixel group (4 px); also pg+8
    const int cs = (tid >> 3) & 1;     // c-half
    const int og = tid >> 4;           // 4 o's

    auto stage_w = [&](int k, int buf) {
        const float* src = g_wt + k * 4096 + tid * 4;
        unsigned dst = (unsigned)__cvta_generic_to_shared(sWb + buf * 4096 + tid * 4);
        #pragma unroll
        for (int j = 0; j < 4; j++) {
            asm volatile("cp.async.cg.shared.global [%0], [%1], 16;"
                         :: "r"(dst + j * 4096), "l"(src + j * 1024) : "memory");
        }
        asm volatile("cp.async.commit_group;" ::: "memory");
    };

    float bsum[4] = {0.f, 0.f, 0.f, 0.f};
    float bsq[4]  = {0.f, 0.f, 0.f, 0.f};

    for (int t = blockIdx.x; t < NTILES; t += DCN_GRID) {
        const int pixbase = t * DCN_PX;

        __syncthreads();    // previous tile fully consumed

        // ---- sampling params for all (k, px) ----
        for (int tt = tid; tt < 9 * DCN_PX; tt += 256) {
            int k  = tt / DCN_PX;
            int px = tt % DCN_PX;
            int pid = pixbase + px;
            int rem = pid & (HWW - 1);
            int h   = rem / WW;
            int w   = rem % WW;
            int ki = k / 3, kj = k % 3;
            float2 d = *(const float2*)(g_off + pid * 20 + 2 * k);
            float py  = d.x + (float)(h - 1 + ki);
            float pxf = d.y + (float)(w - 1 + kj);
            float y0f = floorf(py), x0f = floorf(pxf);
            float wy = py - y0f, wx = pxf - x0f;
            int y0 = (int)y0f, x0 = (int)x0f;
            bool vy0 = (y0 >= 0)  && (y0 <= HH - 1);
            bool vy1 = (y0 >= -1) && (y0 <= HH - 2);
            bool vx0 = (x0 >= 0)  && (x0 <= WW - 1);
            bool vx1 = (x0 >= -1) && (x0 <= WW - 2);
            float4 wv;
            wv.x = (1.f - wy) * (1.f - wx) * ((vy0 && vx0) ? 1.f : 0.f);
            wv.y = (1.f - wy) * wx         * ((vy0 && vx1) ? 1.f : 0.f);
            wv.z = wy * (1.f - wx)         * ((vy1 && vx0) ? 1.f : 0.f);
            wv.w = wy * wx                 * ((vy1 && vx1) ? 1.f : 0.f);
            int y0c = min(max(y0, 0), HH - 1), y1c = min(max(y0 + 1, 0), HH - 1);
            int x0c = min(max(x0, 0), WW - 1), x1c = min(max(x0 + 1, 0), WW - 1);
            int rowb = (pid >> 14) * HH;
            int4 iv;
            iv.x = ((rowb + y0c) * WW + x0c) * 64;
            iv.y = ((rowb + y0c) * WW + x1c) * 64;
            iv.z = ((rowb + y1c) * WW + x0c) * 64;
            iv.w = ((rowb + y1c) * WW + x1c) * 64;
            sPI[tt] = iv;
            sPF[tt] = wv;
        }
        stage_w(0, 0);
        __syncthreads();    // params visible

        ulonglong2 a[2][4];
        float4 wv4[2];

        auto gload = [&](int k, int half) {
            #pragma unroll
            for (int pp = 0; pp < 2; pp++) {
                int px = (half * 2 + pp) * 16 + sub;
                int4 iv = sPI[k * DCN_PX + px];
                wv4[pp] = sPF[k * DCN_PX + px];
                a[pp][0] = *(const ulonglong2*)(g_xt + iv.x + q * 4);
                a[pp][1] = *(const ulonglong2*)(g_xt + iv.y + q * 4);
                a[pp][2] = *(const ulonglong2*)(g_xt + iv.z + q * 4);
                a[pp][3] = *(const ulonglong2*)(g_xt + iv.w + q * 4);
            }
        };
        auto gstore = [&](int half, float* buf) {
            #pragma unroll
            for (int pp = 0; pp < 2; pp++) {
                int px = (half * 2 + pp) * 16 + sub;
                unsigned long long W0 = splat2(wv4[pp].x);
                unsigned long long W1 = splat2(wv4[pp].y);
                unsigned long long W2 = splat2(wv4[pp].z);
                unsigned long long W3 = splat2(wv4[pp].w);
                unsigned long long lo = mul2(a[pp][0].x, W0);
                lo = fma2(a[pp][1].x, W1, lo);
                lo = fma2(a[pp][2].x, W2, lo);
                lo = fma2(a[pp][3].x, W3, lo);
                unsigned long long hi = mul2(a[pp][0].y, W0);
                hi = fma2(a[pp][1].y, W1, hi);
                hi = fma2(a[pp][2].y, W2, hi);
                hi = fma2(a[pp][3].y, W3, hi);
                float2 f01 = unpk2(lo);
                float2 f23 = unpk2(hi);
                float* base = buf + 4*((px >> 2) ^ q) + (px & 3) + (4*q)*PT;
                base[0]    = f01.x;
                base[PT]   = f01.y;
                base[2*PT] = f23.x;
                base[3*PT] = f23.y;
            }
        };

        unsigned long long acc[4][4];
        #pragma unroll
        for (int i = 0; i < 4; i++)
            #pragma unroll
            for (int j = 0; j < 4; j++) acc[i][j] = 0ULL;

        auto compute_half = [&](int k, int h) {
            const float* buf = sS + (k & 1) * (64 * PT);
            const float* wkb = sWb + (k & 1) * 4096 + og * 4;
            #pragma unroll 4
            for (int ci = h * 16; ci < h * 16 + 16; ci++) {
                int c = cs * 32 + ci;
                int key = (c >> 2) & 15;
                const float* row = buf + c * PT;
                ulonglong2 sA = *(const ulonglong2*)(row + 4*(pg ^ key));
                ulonglong2 sB = *(const ulonglong2*)(row + 4*((pg + 8) ^ key));
                float4 w = *(const float4*)(wkb + c * 64);
                unsigned long long w0 = splat2(w.x);
                unsigned long long w1 = splat2(w.y);
                unsigned long long w2 = splat2(w.z);
                unsigned long long w3 = splat2(w.w);
                acc[0][0] = fma2(sA.x, w0, acc[0][0]);
                acc[0][1] = fma2(sA.x, w1, acc[0][1]);
                acc[0][2] = fma2(sA.x, w2, acc[0][2]);
                acc[0][3] = fma2(sA.x, w3, acc[0][3]);
                acc[1][0] = fma2(sA.y, w0, acc[1][0]);
                acc[1][1] = fma2(sA.y, w1, acc[1][1]);
                acc[1][2] = fma2(sA.y, w2, acc[1][2]);
                acc[1][3] = fma2(sA.y, w3, acc[1][3]);
                acc[2][0] = fma2(sB.x, w0, acc[2][0]);
                acc[2][1] = fma2(sB.x, w1, acc[2][1]);
                acc[2][2] = fma2(sB.x, w2, acc[2][2]);
                acc[2][3] = fma2(sB.x, w3, acc[2][3]);
                acc[3][0] = fma2(sB.y, w0, acc[3][0]);
                acc[3][1] = fma2(sB.y, w1, acc[3][1]);
                acc[3][2] = fma2(sB.y, w2, acc[3][2]);
                acc[3][3] = fma2(sB.y, w3, acc[3][3]);
            }
        };

        // prologue gather tap 0
        gload(0, 0); gstore(0, sS);
        gload(0, 1); gstore(1, sS);
        asm volatile("cp.async.wait_group 0;" ::: "memory");
        __syncthreads();

        #pragma unroll 1
        for (int k = 0; k < 9; k++) {
            float* nbuf = sS + ((k + 1) & 1) * (64 * PT);
            if (k < 8) { stage_w(k + 1, (k + 1) & 1); gload(k + 1, 0); }
            compute_half(k, 0);
            if (k < 8) { gstore(0, nbuf); gload(k + 1, 1); }
            compute_half(k, 1);
            if (k < 8) gstore(1, nbuf);
            asm volatile("cp.async.wait_group 0;" ::: "memory");
            __syncthreads();
        }

        // reduce the c-split (partner differs in tid bit3 -> lane xor 8)
        #pragma unroll
        for (int i = 0; i < 4; i++)
            #pragma unroll
            for (int j = 0; j < 4; j++) {
                unsigned long long v = __shfl_xor_sync(0xffffffffu, acc[i][j], 8);
                acc[i][j] = add2(acc[i][j], v);
            }

        int ppb = cs * 2;
        int px0 = pixbase + cs * 32 + pg * 4;
        int b = px0 >> 14;
        int rem0 = px0 & (HWW - 1);
        #pragma unroll
        for (int j = 0; j < 4; j++) {
            int o = og * 4 + j;
            float2 u = unpk2(acc[ppb][j]);
            float2 v = unpk2(acc[ppb + 1][j]);
            float4 st; st.x = u.x; st.y = u.y; st.z = v.x; st.w = v.y;
            *(float4*)(out + (b * 64 + o) * HWW + rem0) = st;
            bsum[j] += u.x + u.y + v.x + v.y;
            bsq[j]  += u.x*u.x + u.y*u.y + v.x*v.x + v.y*v.y;
        }
    }

    // ---- fused BN partials ----
    __syncthreads();
    int gidx = pg | (cs << 3);
    #pragma unroll
    for (int j = 0; j < 4; j++) {
        int o = og * 4 + j;
        sRed[o * 17 + gidx]           = bsum[j];
        sRed[64 * 17 + o * 17 + gidx] = bsq[j];
    }
    __syncthreads();
    if (tid < 64) {
        float s = 0.f, qq = 0.f;
        #pragma unroll
        for (int i = 0; i < 16; i++) {
            s  += sRed[tid * 17 + i];
            qq += sRed[64 * 17 + tid * 17 + i];
        }
        g_part[blockIdx.x * 64 + tid] = make_float2(s, qq);
    }
}

// ---------------------------------------------------------------------------
// Kernel 3: finalize mean / istd
// ---------------------------------------------------------------------------
__global__ void k_bnfin() {
    int o = threadIdx.x;
    float s = 0.f, q = 0.f;
    #pragma unroll 4
    for (int j = 0; j < DCN_GRID; j++) {
        float2 p = g_part[j * 64 + o];
        s += p.x; q += p.y;
    }
    float inv_n = 1.f / (float)(BB * HWW);
    float mean = s * inv_n;
    float var  = q * inv_n - mean * mean;
    g_mean[o] = mean;
    g_istd[o] = rsqrtf(var + 1e-5f);
}

// ---------------------------------------------------------------------------
// Kernel 4: normalize + affine + ReLU
// ---------------------------------------------------------------------------
__global__ __launch_bounds__(256) void k_bnapply(float* __restrict__ out,
                                                 const float* __restrict__ gamma,
                                                 const float* __restrict__ beta) {
    int i4 = blockIdx.x * 256 + threadIdx.x;
    int i = i4 * 4;
    int o = (i / HWW) % 64;
    float scale = g_istd[o] * __ldg(gamma + o);
    float shift = __ldg(beta + o) - g_mean[o] * scale;
    float4 v = *((float4*)out + i4);
    v.x = fmaxf(v.x * scale + shift, 0.f);
    v.y = fmaxf(v.y * scale + shift, 0.f);
    v.z = fmaxf(v.z * scale + shift, 0.f);
    v.w = fmaxf(v.w * scale + shift, 0.f);
    *((float4*)out + i4) = v;
}

// ---------------------------------------------------------------------------
extern "C" void kernel_launch(void* const* d_in, const int* in_sizes, int n_in,
                              void* d_out, int out_size) {
    const float* x     = (const float*)d_in[0];
    const float* ow    = (const float*)d_in[1];
    const float* ob    = (const float*)d_in[2];
    const float* dw    = (const float*)d_in[3];
    const float* gamma = (const float*)d_in[4];
    const float* beta  = (const float*)d_in[5];
    float* out = (float*)d_out;

    k_prep<<<(9*64*64 + 9*64*20 + 255) / 256, 256>>>(dw, ow);

    dim3 tb(32, 8);
    k_transpose<<<dim3(WW / 32, HH, BB), tb>>>(x);

    const int off_smem = (11520 + 8192) * 4;      // 78848
    cudaFuncSetAttribute(k_offconv, cudaFuncAttributeMaxDynamicSharedMemorySize, off_smem);
    k_offconv<<<BB * (HH / 2), 256, off_smem>>>(x, ob);

    const int dcn_smem = 86016;
    cudaFuncSetAttribute(k_dcn, cudaFuncAttributeMaxDynamicSharedMemorySize, dcn_smem);
    k_dcn<<<DCN_GRID, 256, dcn_smem>>>(out);

    k_bnfin<<<1, 64>>>();

    k_bnapply<<<(BB * 64 * HWW / 4) / 256, 256>>>(out, gamma, beta);
}

// round 6
// speedup vs baseline: 2.1273x; 1.1044x over previous
#include <cuda_runtime.h>
#include <cuda_bf16.h>

#define BB 4
#define CC 64
#define HH 128
#define WW 128
#define HWW (HH*WW)
#define NPIX (BB*HH*WW)

#define DCN_PX 64
#define PT 68                      // sample-buffer row pitch (floats)
#define NTILES (NPIX/DCN_PX)       // 1024
#define DCN_GRID 296

// Scratch (allocation-free rule: device globals)
__device__ float g_xt[BB*HH*WW*CC];       // NHWC input (for dcn gathers)
__device__ float g_off[NPIX*20];          // offsets, pitch 20
__device__ float g_wt[9*64*64];           // dcn weights [k][c][o]
__device__ float g_owt[9*64*20];          // offset-conv weights [k][c][20]
__device__ float g_mean[CC];
__device__ float g_istd[CC];
__device__ float2 g_part[DCN_GRID*64];    // fused bnstats partials

// ---------------- packed f32x2 helpers ----------------
__device__ __forceinline__ unsigned long long splat2(float x) {
    unsigned long long r;
    asm("mov.b64 %0, {%1, %1};" : "=l"(r) : "f"(x));
    return r;
}
__device__ __forceinline__ unsigned long long pack2(float x, float y) {
    unsigned long long r;
    asm("mov.b64 %0, {%1, %2};" : "=l"(r) : "f"(x), "f"(y));
    return r;
}
__device__ __forceinline__ unsigned long long fma2(unsigned long long a,
                                                   unsigned long long b,
                                                   unsigned long long c) {
    unsigned long long d;
    asm("fma.rn.f32x2 %0, %1, %2, %3;" : "=l"(d) : "l"(a), "l"(b), "l"(c));
    return d;
}
__device__ __forceinline__ unsigned long long mul2(unsigned long long a,
                                                   unsigned long long b) {
    unsigned long long d;
    asm("mul.rn.f32x2 %0, %1, %2;" : "=l"(d) : "l"(a), "l"(b));
    return d;
}
__device__ __forceinline__ unsigned long long add2(unsigned long long a,
                                                   unsigned long long b) {
    unsigned long long d;
    asm("add.rn.f32x2 %0, %1, %2;" : "=l"(d) : "l"(a), "l"(b));
    return d;
}
__device__ __forceinline__ float2 unpk2(unsigned long long v) {
    float2 f;
    asm("mov.b64 {%0, %1}, %2;" : "=f"(f.x), "=f"(f.y) : "l"(v));
    return f;
}

// ---------------------------------------------------------------------------
// Kernel P: one-time weight transposes.
// ---------------------------------------------------------------------------
__global__ void k_prep(const float* __restrict__ dw, const float* __restrict__ ow) {
    int idx = blockIdx.x * 256 + threadIdx.x;
    if (idx < 9*64*64) {
        int k = idx / 4096;
        int r = idx % 4096;
        int c = r / 64;
        int o = r % 64;
        g_wt[idx] = dw[(o*64 + c)*9 + k];
    } else {
        int j = idx - 9*64*64;
        if (j < 9*64*20) {
            int k = j / 1280;
            int r = j % 1280;
            int c = r / 20;
            int o = r % 20;
            g_owt[j] = (o < 18) ? ow[(o*64 + c)*9 + k] : 0.f;
        }
    }
}

// ---------------------------------------------------------------------------
// Kernel 0: NCHW -> NHWC transpose
// ---------------------------------------------------------------------------
__global__ void k_transpose(const float* __restrict__ x) {
    __shared__ float s[64][33];
    int w0 = blockIdx.x * 32;
    int h  = blockIdx.y;
    int b  = blockIdx.z;
    int tx = threadIdx.x, ty = threadIdx.y;
    #pragma unroll
    for (int c = ty; c < 64; c += 8)
        s[c][tx] = x[((b*64 + c)*HH + h)*WW + w0 + tx];
    __syncthreads();
    int pixbase = (b*HH + h)*WW + w0;
    #pragma unroll
    for (int wi = ty; wi < 32; wi += 8) {
        g_xt[(pixbase + wi)*64 + tx]      = s[tx][wi];
        g_xt[(pixbase + wi)*64 + 32 + tx] = s[32 + tx][wi];
    }
}

// ---------------------------------------------------------------------------
// Kernel 1: offset conv 3x3, 64 -> 18ch. Reads NCHW x (coalesced). (as R5)
// ---------------------------------------------------------------------------
__global__ __launch_bounds__(256) void k_offconv(const float* __restrict__ x,
                                                 const float* __restrict__ ob) {
    extern __shared__ float sm[];
    float* sOW = sm;                 // 11520 floats
    float* xt  = sm + 11520;         // 8192 floats

    int tid = threadIdx.x;
    for (int i4 = tid; i4 < 2880; i4 += 256)
        ((float4*)sOW)[i4] = ((const float4*)g_owt)[i4];

    int b  = blockIdx.x >> 6;
    int y0 = (blockIdx.x & 63) * 2;
    int py = tid >> 7;               // 0..1
    int w  = tid & 127;

    unsigned long long acc[9];
    #pragma unroll
    for (int j = 0; j < 9; j++) acc[j] = pack2(__ldg(ob + 2*j), __ldg(ob + 2*j + 1));

    #pragma unroll 1
    for (int cc = 0; cc < 4; cc++) {
        __syncthreads();
        #pragma unroll
        for (int j = 0; j < 8; j++) {
            int i4 = tid + j * 256;
            int ci = i4 >> 7;
            int r  = (i4 >> 5) & 3;
            int w4 = i4 & 31;
            int yr = y0 - 1 + r;
            float4 v = make_float4(0.f, 0.f, 0.f, 0.f);
            if (yr >= 0 && yr < HH)
                v = *((const float4*)(x + ((b*64 + cc*16 + ci)*HH + yr)*WW) + w4);
            ((float4*)xt)[i4] = v;
        }
        __syncthreads();

        #pragma unroll
        for (int ki = 0; ki < 3; ki++) {
            int r = py + ki;
            #pragma unroll
            for (int kj = 0; kj < 3; kj++) {
                int xx = w - 1 + kj;
                if (xx < 0 || xx >= WW) continue;
                const float* wk0 = sOW + ((ki*3 + kj)*64 + cc*16) * 20;
                const float* xr = xt + r*128 + xx;
                #pragma unroll 4
                for (int ci = 0; ci < 16; ci++) {
                    unsigned long long s2 = splat2(xr[ci * 512]);
                    const float* wr = wk0 + ci * 20;
                    const ulonglong2* w2 = (const ulonglong2*)wr;
                    ulonglong2 wa = w2[0];
                    ulonglong2 wb = w2[1];
                    unsigned long long wc = *(const unsigned long long*)(wr + 16);
                    acc[0] = fma2(s2, wa.x, acc[0]);
                    acc[1] = fma2(s2, wa.y, acc[1]);
                    acc[2] = fma2(s2, wb.x, acc[2]);
                    acc[3] = fma2(s2, wb.y, acc[3]);
                    acc[8] = fma2(s2, wc,   acc[8]);
                    const ulonglong2* w3 = (const ulonglong2*)(wr + 8);
                    ulonglong2 wd = w3[0];
                    ulonglong2 we = w3[1];
                    acc[4] = fma2(s2, wd.x, acc[4]);
                    acc[5] = fma2(s2, wd.y, acc[5]);
                    acc[6] = fma2(s2, we.x, acc[6]);
                    acc[7] = fma2(s2, we.y, acc[7]);
                }
            }
        }
    }
    int pid = b * HWW + (y0 + py) * WW + w;
    float2* op = (float2*)(g_off + pid * 20);
    #pragma unroll
    for (int j = 0; j < 9; j++) op[j] = unpk2(acc[j]);
}

// ---------------------------------------------------------------------------
// Kernel 2: deformable sampling + DCN conv.
// Warp tile 64px x 32o; 4-way c-split across warps (smem-reduced at tile end);
// thread = 8px x 8o (acc[4 pxpair][8 o]).
// Sample buffer layout: row c (pitch PT), chunk perm(p,c)=((p^q)+(q>>3))&15,
// q=(c>>2): conflict-free STS and LDS.
// smem: samples 2x17408 + weights 2x16384 + params 18432 = 86016 -> 2 blk/SM
// ---------------------------------------------------------------------------
__global__ __launch_bounds__(256, 2) void k_dcn(float* __restrict__ out) {
    extern __shared__ char smem[];
    float*  sS  = (float*)smem;                     // [2][64][PT]
    float*  sWb = (float*)(smem + 34816);           // [2][4096]
    float*  sRed = (float*)(smem + 34816);          // reduce region (reuses sWb)
    int4*   sPI = (int4*)(smem + 67584);            // [9*64]
    float4* sPF = (float4*)(smem + 76800);          // [9*64]

    const int tid = threadIdx.x;
    // gather mapping
    const int q   = tid & 15;          // channel chunk (4 c's)
    const int sub = tid >> 4;          // pixel-within-pass
    // compute mapping
    const int lane = tid & 31;
    const int wid  = tid >> 5;
    const int Q    = wid & 1;          // o half
    const int ch   = wid >> 1;         // c quarter (16 c's)
    const int pg   = lane & 7;         // pixel quad
    const int osub = (lane >> 3) & 3;
    const int obase = 32*Q + 8*osub;   // 8 o's per thread

    auto stage_w = [&](int k, int buf) {
        const float* src = g_wt + k * 4096 + tid * 4;
        unsigned dst = (unsigned)__cvta_generic_to_shared(sWb + buf * 4096 + tid * 4);
        #pragma unroll
        for (int j = 0; j < 4; j++) {
            asm volatile("cp.async.cg.shared.global [%0], [%1], 16;"
                         :: "r"(dst + j * 4096), "l"(src + j * 1024) : "memory");
        }
        asm volatile("cp.async.commit_group;" ::: "memory");
    };

    float bsum[8], bsq[8];
    #pragma unroll
    for (int j = 0; j < 8; j++) { bsum[j] = 0.f; bsq[j] = 0.f; }

    for (int t = blockIdx.x; t < NTILES; t += DCN_GRID) {
        const int pixbase = t * DCN_PX;

        __syncthreads();   // previous tile's reduce/writes done

        // ---- sampling params for all (k, px) ----
        for (int tt = tid; tt < 9 * DCN_PX; tt += 256) {
            int k  = tt / DCN_PX;
            int px = tt % DCN_PX;
            int pid = pixbase + px;
            int rem = pid & (HWW - 1);
            int h   = rem / WW;
            int w   = rem % WW;
            int ki = k / 3, kj = k % 3;
            float2 d = *(const float2*)(g_off + pid * 20 + 2 * k);
            float py  = d.x + (float)(h - 1 + ki);
            float pxf = d.y + (float)(w - 1 + kj);
            float y0f = floorf(py), x0f = floorf(pxf);
            float wy = py - y0f, wx = pxf - x0f;
            int y0 = (int)y0f, x0 = (int)x0f;
            bool vy0 = (y0 >= 0)  && (y0 <= HH - 1);
            bool vy1 = (y0 >= -1) && (y0 <= HH - 2);
            bool vx0 = (x0 >= 0)  && (x0 <= WW - 1);
            bool vx1 = (x0 >= -1) && (x0 <= WW - 2);
            float4 wv;
            wv.x = (1.f - wy) * (1.f - wx) * ((vy0 && vx0) ? 1.f : 0.f);
            wv.y = (1.f - wy) * wx         * ((vy0 && vx1) ? 1.f : 0.f);
            wv.z = wy * (1.f - wx)         * ((vy1 && vx0) ? 1.f : 0.f);
            wv.w = wy * wx                 * ((vy1 && vx1) ? 1.f : 0.f);
            int y0c = min(max(y0, 0), HH - 1), y1c = min(max(y0 + 1, 0), HH - 1);
            int x0c = min(max(x0, 0), WW - 1), x1c = min(max(x0 + 1, 0), WW - 1);
            int rowb = (pid >> 14) * HH;
            int4 iv;
            iv.x = ((rowb + y0c) * WW + x0c) * 64;
            iv.y = ((rowb + y0c) * WW + x1c) * 64;
            iv.z = ((rowb + y1c) * WW + x0c) * 64;
            iv.w = ((rowb + y1c) * WW + x1c) * 64;
            sPI[tt] = iv;
            sPF[tt] = wv;
        }
        stage_w(0, 0);
        __syncthreads();   // params visible

        ulonglong2 a[4];
        float4 wvf;

        auto gload = [&](int k, int pp) {
            int px = pp * 16 + sub;
            int4 iv = sPI[k * DCN_PX + px];
            wvf = sPF[k * DCN_PX + px];
            a[0] = *(const ulonglong2*)(g_xt + iv.x + q * 4);
            a[1] = *(const ulonglong2*)(g_xt + iv.y + q * 4);
            a[2] = *(const ulonglong2*)(g_xt + iv.z + q * 4);
            a[3] = *(const ulonglong2*)(g_xt + iv.w + q * 4);
        };
        auto gstore = [&](int pp, float* buf) {
            int px = pp * 16 + sub;
            unsigned long long W0 = splat2(wvf.x);
            unsigned long long W1 = splat2(wvf.y);
            unsigned long long W2 = splat2(wvf.z);
            unsigned long long W3 = splat2(wvf.w);
            unsigned long long lo = mul2(a[0].x, W0);
            lo = fma2(a[1].x, W1, lo);
            lo = fma2(a[2].x, W2, lo);
            lo = fma2(a[3].x, W3, lo);
            unsigned long long hi = mul2(a[0].y, W0);
            hi = fma2(a[1].y, W1, hi);
            hi = fma2(a[2].y, W2, hi);
            hi = fma2(a[3].y, W3, hi);
            float2 f01 = unpk2(lo);
            float2 f23 = unpk2(hi);
            int perm = (((px >> 2) ^ q) + (q >> 3)) & 15;
            float* base = buf + (4*q)*PT + 4*perm + (px & 3);
            base[0]    = f01.x;
            base[PT]   = f01.y;
            base[2*PT] = f23.x;
            base[3*PT] = f23.y;
        };

        unsigned long long acc[4][8];
        #pragma unroll
        for (int i = 0; i < 4; i++)
            #pragma unroll
            for (int j = 0; j < 8; j++) acc[i][j] = 0ULL;

        auto compute_c = [&](int c, const float* buf, const float* wcur) {
            int qc = c >> 2;
            int s  = qc >> 3;
            int permA = ((pg ^ qc) + s) & 15;
            int permB = (((pg + 8) ^ qc) + s) & 15;
            const float* row = buf + c * PT;
            ulonglong2 sA = *(const ulonglong2*)(row + 4*permA);
            ulonglong2 sB = *(const ulonglong2*)(row + 4*permB);
            const float* wp = wcur + c * 64 + obase;
            float4 wa = *(const float4*)(wp);
            float4 wb = *(const float4*)(wp + 4);
            unsigned long long w0 = splat2(wa.x);
            unsigned long long w1 = splat2(wa.y);
            unsigned long long w2 = splat2(wa.z);
            unsigned long long w3 = splat2(wa.w);
            unsigned long long w4 = splat2(wb.x);
            unsigned long long w5 = splat2(wb.y);
            unsigned long long w6 = splat2(wb.z);
            unsigned long long w7 = splat2(wb.w);
            acc[0][0] = fma2(sA.x, w0, acc[0][0]);
            acc[0][1] = fma2(sA.x, w1, acc[0][1]);
            acc[0][2] = fma2(sA.x, w2, acc[0][2]);
            acc[0][3] = fma2(sA.x, w3, acc[0][3]);
            acc[0][4] = fma2(sA.x, w4, acc[0][4]);
            acc[0][5] = fma2(sA.x, w5, acc[0][5]);
            acc[0][6] = fma2(sA.x, w6, acc[0][6]);
            acc[0][7] = fma2(sA.x, w7, acc[0][7]);
            acc[1][0] = fma2(sA.y, w0, acc[1][0]);
            acc[1][1] = fma2(sA.y, w1, acc[1][1]);
            acc[1][2] = fma2(sA.y, w2, acc[1][2]);
            acc[1][3] = fma2(sA.y, w3, acc[1][3]);
            acc[1][4] = fma2(sA.y, w4, acc[1][4]);
            acc[1][5] = fma2(sA.y, w5, acc[1][5]);
            acc[1][6] = fma2(sA.y, w6, acc[1][6]);
            acc[1][7] = fma2(sA.y, w7, acc[1][7]);
            acc[2][0] = fma2(sB.x, w0, acc[2][0]);
            acc[2][1] = fma2(sB.x, w1, acc[2][1]);
            acc[2][2] = fma2(sB.x, w2, acc[2][2]);
            acc[2][3] = fma2(sB.x, w3, acc[2][3]);
            acc[2][4] = fma2(sB.x, w4, acc[2][4]);
            acc[2][5] = fma2(sB.x, w5, acc[2][5]);
            acc[2][6] = fma2(sB.x, w6, acc[2][6]);
            acc[2][7] = fma2(sB.x, w7, acc[2][7]);
            acc[3][0] = fma2(sB.y, w0, acc[3][0]);
            acc[3][1] = fma2(sB.y, w1, acc[3][1]);
            acc[3][2] = fma2(sB.y, w2, acc[3][2]);
            acc[3][3] = fma2(sB.y, w3, acc[3][3]);
            acc[3][4] = fma2(sB.y, w4, acc[3][4]);
            acc[3][5] = fma2(sB.y, w5, acc[3][5]);
            acc[3][6] = fma2(sB.y, w6, acc[3][6]);
            acc[3][7] = fma2(sB.y, w7, acc[3][7]);
        };

        // prologue: gather tap 0
        #pragma unroll
        for (int pp = 0; pp < 4; pp++) {
            gload(0, pp);
            gstore(pp, sS);
        }
        asm volatile("cp.async.wait_group 0;" ::: "memory");
        __syncthreads();

        #pragma unroll 1
        for (int k = 0; k < 9; k++) {
            const float* buf  = sS + (k & 1) * (64 * PT);
            float* nbuf       = sS + ((k + 1) & 1) * (64 * PT);
            const float* wcur = sWb + (k & 1) * 4096;
            if (k < 8) stage_w(k + 1, (k + 1) & 1);
            #pragma unroll
            for (int pp = 0; pp < 4; pp++) {
                if (k < 8) gload(k + 1, pp);
                int c0 = 16 * ch + 4 * pp;
                compute_c(c0 + 0, buf, wcur);
                compute_c(c0 + 1, buf, wcur);
                compute_c(c0 + 2, buf, wcur);
                compute_c(c0 + 3, buf, wcur);
                if (k < 8) gstore(pp, nbuf);
            }
            asm volatile("cp.async.wait_group 0;" ::: "memory");
            __syncthreads();
        }

        // ---- cross-warp c-split reduction (4 -> 1) through smem ----
        float* RA = sRed;              // 4096 floats (16KB)
        float* RB = sRed + 4096;       // 4096 floats

        auto store_acc = [&](float* R) {
            #pragma unroll
            for (int i = 0; i < 16; i++) {
                int pi = i >> 2, j2 = (i & 3) * 2;
                ulonglong2 v;
                v.x = acc[pi][j2];
                v.y = acc[pi][j2 + 1];
                *(ulonglong2*)(R + Q*2048 + i*128 + lane*4) = v;
            }
        };
        auto load_add = [&](const float* R) {
            #pragma unroll
            for (int i = 0; i < 16; i++) {
                int pi = i >> 2, j2 = (i & 3) * 2;
                ulonglong2 v = *(const ulonglong2*)(R + Q*2048 + i*128 + lane*4);
                acc[pi][j2]     = add2(acc[pi][j2], v.x);
                acc[pi][j2 + 1] = add2(acc[pi][j2 + 1], v.y);
            }
        };

        if (ch == 1) store_acc(RA);
        if (ch == 3) store_acc(RB);
        __syncthreads();
        if (ch == 0) load_add(RA);
        if (ch == 2) load_add(RB);
        __syncthreads();
        if (ch == 2) store_acc(RA);
        __syncthreads();
        if (ch == 0) load_add(RA);

        // ---- epilogue: warps 0,1 hold full sums; write NCHW + BN partials --
        if (wid < 2) {
            int b = pixbase >> 14;
            int rem0 = pixbase & (HWW - 1);
            #pragma unroll
            for (int pi = 0; pi < 4; pi++) {
                int pxl = 4*pg + (pi & 1)*2 + (pi >> 1)*32;
                #pragma unroll
                for (int j = 0; j < 8; j++) {
                    int o = obase + j;
                    float2 f = unpk2(acc[pi][j]);
                    *(float2*)(out + (b*64 + o)*HWW + rem0 + pxl) = f;
                    bsum[j] += f.x + f.y;
                    bsq[j]  += f.x*f.x + f.y*f.y;
                }
            }
        }
    }

    // ---- final BN partials: reduce over pg lanes, write per-block ----
    if (wid < 2) {
        #pragma unroll
        for (int j = 0; j < 8; j++) {
            #pragma unroll
            for (int d = 1; d < 8; d <<= 1) {
                bsum[j] += __shfl_xor_sync(0xffffffffu, bsum[j], d);
                bsq[j]  += __shfl_xor_sync(0xffffffffu, bsq[j],  d);
            }
        }
        if (pg == 0) {
            #pragma unroll
            for (int j = 0; j < 8; j++)
                g_part[blockIdx.x * 64 + obase + j] = make_float2(bsum[j], bsq[j]);
        }
    }
}

// ---------------------------------------------------------------------------
// Kernel 3: finalize mean / istd
// ---------------------------------------------------------------------------
__global__ void k_bnfin() {
    int o = threadIdx.x;
    float s = 0.f, q = 0.f;
    #pragma unroll 4
    for (int j = 0; j < DCN_GRID; j++) {
        float2 p = g_part[j * 64 + o];
        s += p.x; q += p.y;
    }
    float inv_n = 1.f / (float)(BB * HWW);
    float mean = s * inv_n;
    float var  = q * inv_n - mean * mean;
    g_mean[o] = mean;
    g_istd[o] = rsqrtf(var + 1e-5f);
}

// ---------------------------------------------------------------------------
// Kernel 4: normalize + affine + ReLU
// ---------------------------------------------------------------------------
__global__ __launch_bounds__(256) void k_bnapply(float* __restrict__ out,
                                                 const float* __restrict__ gamma,
                                                 const float* __restrict__ beta) {
    int i4 = blockIdx.x * 256 + threadIdx.x;
    int i = i4 * 4;
    int o = (i / HWW) % 64;
    float scale = g_istd[o] * __ldg(gamma + o);
    float shift = __ldg(beta + o) - g_mean[o] * scale;
    float4 v = *((float4*)out + i4);
    v.x = fmaxf(v.x * scale + shift, 0.f);
    v.y = fmaxf(v.y * scale + shift, 0.f);
    v.z = fmaxf(v.z * scale + shift, 0.f);
    v.w = fmaxf(v.w * scale + shift, 0.f);
    *((float4*)out + i4) = v;
}

// ---------------------------------------------------------------------------
extern "C" void kernel_launch(void* const* d_in, const int* in_sizes, int n_in,
                              void* d_out, int out_size) {
    const float* x     = (const float*)d_in[0];
    const float* ow    = (const float*)d_in[1];
    const float* ob    = (const float*)d_in[2];
    const float* dw    = (const float*)d_in[3];
    const float* gamma = (const float*)d_in[4];
    const float* beta  = (const float*)d_in[5];
    float* out = (float*)d_out;

    k_prep<<<(9*64*64 + 9*64*20 + 255) / 256, 256>>>(dw, ow);

    dim3 tb(32, 8);
    k_transpose<<<dim3(WW / 32, HH, BB), tb>>>(x);

    const int off_smem = (11520 + 8192) * 4;      // 78848
    cudaFuncSetAttribute(k_offconv, cudaFuncAttributeMaxDynamicSharedMemorySize, off_smem);
    k_offconv<<<BB * (HH / 2), 256, off_smem>>>(x, ob);

    const int dcn_smem = 86016;
    cudaFuncSetAttribute(k_dcn, cudaFuncAttributeMaxDynamicSharedMemorySize, dcn_smem);
    k_dcn<<<DCN_GRID, 256, dcn_smem>>>(out);

    k_bnfin<<<1, 64>>>();

    k_bnapply<<<(BB * 64 * HWW / 4) / 256, 256>>>(out, gamma, beta);
}